// round 8
// baseline (speedup 1.0000x reference)
#include <cuda_runtime.h>
#include <cuda_bf16.h>
#include <math.h>

#define BATCH   512
#define T_STEPS 512
#define CHAN    32
#define CIN     33
#define HID     128
#define GATES   512   // 4*H
#define EPSF    1e-12f

typedef unsigned long long ull_t;

// ---------------------------------------------------------------------------
// f32x2 packed-math helpers (Blackwell FFMA2 path — only reachable via PTX)
// ---------------------------------------------------------------------------
__device__ __forceinline__ void ffma2(ull_t& d, ull_t a, ull_t b) {
    asm("fma.rn.f32x2 %0, %1, %2, %0;" : "+l"(d) : "l"(a), "l"(b));
}
// (bf16_lo, bf16_hi) packed in u32 -> (f32_lo, f32_hi) packed b64 (pure ALU)
__device__ __forceinline__ ull_t bf2_to_f32x2(unsigned int u) {
    ull_t r;
    asm("{\n\t.reg .b32 lo, hi;\n\t"
        "shl.b32 lo, %1, 16;\n\t"
        "and.b32 hi, %1, 0xFFFF0000;\n\t"
        "mov.b64 %0, {lo, hi};\n\t}" : "=l"(r) : "r"(u));
    return r;
}
__device__ __forceinline__ ull_t pack_dup(float v) {
    ull_t r; unsigned int b = __float_as_uint(v);
    asm("mov.b64 %0, {%1, %1};" : "=l"(r) : "r"(b));
    return r;
}
__device__ __forceinline__ float2 unpack2(ull_t d) {
    unsigned int lo, hi;
    asm("mov.b64 {%0, %1}, %2;" : "=r"(lo), "=r"(hi) : "l"(d));
    return make_float2(__uint_as_float(lo), __uint_as_float(hi));
}
__device__ __forceinline__ float hsum2(ull_t d) {
    float2 f = unpack2(d); return f.x + f.y;
}
__device__ __forceinline__ unsigned int pack_bf2(float a, float b) {
    unsigned int ua = (unsigned int)__bfloat16_as_ushort(__float2bfloat16(a));
    unsigned int ub = (unsigned int)__bfloat16_as_ushort(__float2bfloat16(b));
    return ua | (ub << 16);
}

// ---------------------------------------------------------------------------
// Device scratch (static; allocations are forbidden)
// ---------------------------------------------------------------------------
__device__ float        g_std_arr[T_STEPS];             // minibatch-std scalar per t
__device__ float        g_inv_arr[4];                   // 1/sigma: ih, hh, fc
__device__ float        g_wt[CIN * GATES];              // Wih^T scaled: [33][512]
__device__ float        g_bias[GATES];                  // b_ih + b_hh
__device__ unsigned int g_whh_q[(HID / 4) * GATES * 2]; // bf16 k-quads: [32 k4][512 g][2]
__device__ float        g_gates[(size_t)BATCH * T_STEPS * GATES]; // 536 MB gates_x

// ---------------------------------------------------------------------------
// Kernel A: minibatch std feature. grid=T, block=256 (8 b-seg x 32 chan)
// ---------------------------------------------------------------------------
__global__ void std_kernel(const float* __restrict__ x)
{
    int t   = blockIdx.x;
    int tid = threadIdx.x;
    int c   = tid & 31;
    int seg = tid >> 5;

    float s = 0.f, ss = 0.f;
    for (int b = seg; b < BATCH; b += 8) {
        float v = x[((size_t)b * T_STEPS + t) * CHAN + c];
        s  += v;
        ss += v * v;
    }
    __shared__ float sm1[256], sm2[256];
    sm1[tid] = s; sm2[tid] = ss;
    __syncthreads();
    if (seg == 0) {
        for (int k = 1; k < 8; k++) { s += sm1[k * 32 + c]; ss += sm2[k * 32 + c]; }
        float mean = s * (1.f / 512.f);
        float var  = (ss - 512.f * mean * mean) * (1.f / 511.f);
        float sd   = sqrtf(fmaxf(var, 0.f));
        #pragma unroll
        for (int off = 16; off; off >>= 1)
            sd += __shfl_xor_sync(0xffffffffu, sd, off);
        if (c == 0) g_std_arr[t] = sd * (1.f / 32.f);
    }
}

// ---------------------------------------------------------------------------
// Kernel B: spectral norms (one power iteration, matching reference exactly)
// then scale+transpose Wih, combine bias, quantize Whh to bf16 k-quads.
// single block, 512 threads
// ---------------------------------------------------------------------------
__global__ void prep_kernel(const float* __restrict__ wih, const float* __restrict__ uih,
                            const float* __restrict__ whh, const float* __restrict__ uhh,
                            const float* __restrict__ bih, const float* __restrict__ bhh,
                            const float* __restrict__ wfc, const float* __restrict__ ufc)
{
    __shared__ float tv[HID];
    __shared__ float red[512];
    __shared__ float nrm;
    __shared__ float inv_s[4];
    int tid = threadIdx.x;

    // ---- ih: W [512,33] ----
    if (tid < CIN) {
        float s = 0.f;
        for (int g = 0; g < GATES; g++) s += wih[g * CIN + tid] * uih[g];
        tv[tid] = s;
    }
    __syncthreads();
    if (tid == 0) {
        float n = 0.f;
        for (int c = 0; c < CIN; c++) n += tv[c] * tv[c];
        nrm = sqrtf(n) + EPSF;
    }
    __syncthreads();
    {
        float a = 0.f;
        for (int c = 0; c < CIN; c++) a += wih[tid * CIN + c] * tv[c];
        a /= nrm;
        red[tid] = a * a;
    }
    __syncthreads();
    for (int off = 256; off; off >>= 1) {
        if (tid < off) red[tid] += red[tid + off];
        __syncthreads();
    }
    if (tid == 0) {
        float ssum = red[0];                      // ||W v||^2
        float v = (sqrtf(ssum) + EPSF) / ssum;    // 1/sigma
        g_inv_arr[0] = v; inv_s[0] = v;
    }
    __syncthreads();

    // ---- hh: W [512,128] ----
    if (tid < HID) {
        float s = 0.f;
        for (int g = 0; g < GATES; g++) s += whh[g * HID + tid] * uhh[g];
        tv[tid] = s;
    }
    __syncthreads();
    if (tid == 0) {
        float n = 0.f;
        for (int k = 0; k < HID; k++) n += tv[k] * tv[k];
        nrm = sqrtf(n) + EPSF;
    }
    __syncthreads();
    {
        float a = 0.f;
        for (int k = 0; k < HID; k++) a += whh[tid * HID + k] * tv[k];
        a /= nrm;
        red[tid] = a * a;
    }
    __syncthreads();
    for (int off = 256; off; off >>= 1) {
        if (tid < off) red[tid] += red[tid + off];
        __syncthreads();
    }
    if (tid == 0) {
        float ssum = red[0];
        float v = (sqrtf(ssum) + EPSF) / ssum;
        g_inv_arr[1] = v; inv_s[1] = v;
    }
    __syncthreads();

    // ---- fc: W [1,128] ----
    red[tid] = (tid < HID) ? wfc[tid] * wfc[tid] : 0.f;
    __syncthreads();
    for (int off = 256; off; off >>= 1) {
        if (tid < off) red[tid] += red[tid + off];
        __syncthreads();
    }
    if (tid == 0) {
        float wn2 = red[0];
        float u0  = ufc[0];
        float tn  = fabsf(u0) * sqrtf(wn2) + EPSF;   // ||W^T u||
        float s   = u0 * wn2 / tn;                   // W @ v (scalar)
        float sig = s * s / (fabsf(s) + EPSF);
        float v = 1.f / sig;
        g_inv_arr[2] = v; inv_s[2] = v;
    }
    __syncthreads();

    // ---- scale + pack ----
    float i0 = inv_s[0], i1 = inv_s[1];
    // Wih transposed & scaled: g_wt[c*512+g]
    for (int c = 0; c < CIN; c++)
        g_wt[c * GATES + tid] = wih[tid * CIN + c] * i0;
    g_bias[tid] = bih[tid] + bhh[tid];
    // Whh scaled -> bf16 k-quads: g_whh_q[k4*1024 + g*2 + {0,1}]
    for (int k4 = 0; k4 < HID / 4; k4++) {
        float w0 = whh[tid * HID + 4 * k4]     * i1;
        float w1 = whh[tid * HID + 4 * k4 + 1] * i1;
        float w2 = whh[tid * HID + 4 * k4 + 2] * i1;
        float w3 = whh[tid * HID + 4 * k4 + 3] * i1;
        g_whh_q[k4 * (GATES * 2) + tid * 2]     = pack_bf2(w0, w1);
        g_whh_q[k4 * (GATES * 2) + tid * 2 + 1] = pack_bf2(w2, w3);
    }
}

// ---------------------------------------------------------------------------
// Kernel C: gates_x = x_aug @ Wih_n^T + bias (f32x2 packed over gate pairs).
// grid = 8192 blocks x 32 rows, 256 threads; thread t owns gates (2t, 2t+1).
// ---------------------------------------------------------------------------
__global__ void gates_kernel(const float* __restrict__ x)
{
    __shared__ ull_t xs_d[CIN * 34];   // x duplicated (v,v), [c][34 rows]
    int row0 = blockIdx.x * 32;
    int tid  = threadIdx.x;

    for (int i = tid; i < 32 * CHAN; i += 256) {
        int r = i >> 5, c = i & 31;
        xs_d[c * 34 + r] = pack_dup(x[(size_t)(row0 + r) * CHAN + c]);
    }
    if (tid < 32)
        xs_d[CHAN * 34 + tid] = pack_dup(g_std_arr[(row0 + tid) & (T_STEPS - 1)]);
    __syncthreads();

    const ull_t* wt2   = (const ull_t*)g_wt;     // (w_2t, w_2t+1) f32 pairs
    const ull_t* bias2 = (const ull_t*)g_bias;
    ull_t*       gout  = (ull_t*)g_gates;
    ull_t bp = bias2[tid];

    for (int rb = 0; rb < 32; rb += 8) {
        ull_t acc[8];
        #pragma unroll
        for (int r = 0; r < 8; r++) acc[r] = bp;
        #pragma unroll
        for (int c = 0; c < CIN; c++) {
            ull_t w = wt2[c * (GATES / 2) + tid];
            #pragma unroll
            for (int r = 0; r < 8; r++)
                ffma2(acc[r], w, xs_d[c * 34 + rb + r]);
        }
        #pragma unroll
        for (int r = 0; r < 8; r++)
            gout[(size_t)(row0 + rb + r) * (GATES / 2) + tid] = acc[r];
    }
}

// ---------------------------------------------------------------------------
// Kernel D: persistent LSTM + online-softmax attention + FC epilogue.
// 128 blocks x 4 batch rows, 512 threads (4 warps/SMSP), 512 steps.
// Matvec: thread t owns gate g=t for all 4 rows (f32x2 over k, LDS.128 h).
// Pointwise: thread t owns slot (r = t>>7, j = t&127), c-state in register.
// ---------------------------------------------------------------------------
__device__ __forceinline__ float sigmoidf_(float x) {
    return 1.f / (1.f + __expf(-x));
}

__global__ void __launch_bounds__(512, 1)
lstm_kernel(const float* __restrict__ attn_w,
            const float* __restrict__ fc_w,
            const float* __restrict__ fc_b,
            float* __restrict__ out)
{
    extern __shared__ unsigned char smem_raw[];
    unsigned int* wsm = (unsigned int*)smem_raw;                 // [32 k4][512 g][2] bf16
    float* h_s  = (float*)(smem_raw + (HID / 4) * GATES * 2 * 4);// [4][128] (16B aligned)
    float* gts  = h_s + 4 * HID;                                 // [4][512]
    float* aw_s = gts + 4 * GATES;                               // [128]
    float* fw_s = aw_s + HID;                                    // [128]
    float* lpart= fw_s + HID;                                    // [16] warp partials
    float* mrow = lpart + 16;                                    // [4]
    float* srow = mrow + 4;                                      // [4]
    float* alph = srow + 4;                                      // [4]
    float* prow = alph + 4;                                      // [4]

    int tid  = threadIdx.x;
    int b0   = blockIdx.x * 4;
    int wid  = tid >> 5, lane = tid & 31;
    int r_pw = tid >> 7, j_pw = tid & 127;

    // init smem
    for (int i = tid; i < (HID / 4) * GATES * 2; i += 512) wsm[i] = g_whh_q[i];
    if (tid < 4 * HID) h_s[tid] = 0.f;
    if (tid < HID) { aw_s[tid] = attn_w[tid]; fw_s[tid] = fc_w[tid]; }
    if (tid < 4)   { mrow[tid] = -INFINITY; srow[tid] = 0.f; }
    __syncthreads();

    float cst  = 0.f;   // cell state for slot (r_pw, j_pw)
    float accp = 0.f;   // online pooled accumulator for slot

    const ull_t*  wq = (const ull_t*)wsm;       // [32][512] ull: 4 bf16 k-weights of gate
    const float4* h4 = (const float4*)h_s;      // [4][32] float4
    const float*  gsrc = g_gates;

    for (int t = 0; t < T_STEPS; t++) {
        // prefetch gates_x (coalesced; latency hidden under the matvec)
        float gx[4];
        #pragma unroll
        for (int r = 0; r < 4; r++)
            gx[r] = gsrc[((size_t)(b0 + r) * T_STEPS + t) * GATES + tid];

        // gates += h @ Whh^T   (4 rows, 1 gate/thread, f32x2 over k-parity)
        ull_t a[4] = {0, 0, 0, 0};
        #pragma unroll 8
        for (int k4 = 0; k4 < HID / 4; k4++) {
            ull_t wp_ = wq[k4 * GATES + tid];           // LDS.64, conflict-free
            unsigned int wlo = (unsigned int)wp_;
            unsigned int whi = (unsigned int)(wp_ >> 32);
            ull_t w0 = bf2_to_f32x2(wlo);               // k = 4k4, 4k4+1
            ull_t w1 = bf2_to_f32x2(whi);               // k = 4k4+2, 4k4+3
            #pragma unroll
            for (int r = 0; r < 4; r++) {
                float4 hv = h4[r * (HID / 4) + k4];     // LDS.128 broadcast
                ull_t h01, h23;
                asm("mov.b64 %0, {%2, %3}; mov.b64 %1, {%4, %5};"
                    : "=l"(h01), "=l"(h23)
                    : "r"(__float_as_uint(hv.x)), "r"(__float_as_uint(hv.y)),
                      "r"(__float_as_uint(hv.z)), "r"(__float_as_uint(hv.w)));
                ffma2(a[r], w0, h01);
                ffma2(a[r], w1, h23);
            }
        }
        #pragma unroll
        for (int r = 0; r < 4; r++)
            gts[r * GATES + tid] = hsum2(a[r]) + gx[r];
        __syncthreads();                                 // sync1: gates ready

        // pointwise LSTM cell (1 slot/thread)
        const float* gr = &gts[r_pw * GATES];
        float gi = gr[j_pw], gf = gr[HID + j_pw];
        float gg = gr[2 * HID + j_pw], go = gr[3 * HID + j_pw];
        float iv = sigmoidf_(gi);
        float fv = sigmoidf_(gf);
        float gv = tanhf(gg);
        float ov = sigmoidf_(go);
        float c  = fv * cst + iv * gv;
        cst      = c;
        float hv = ov * tanhf(c);
        h_s[r_pw * HID + j_pw] = hv;

        // attention partial: per-warp shuffle reduce of h*aw
        float part = hv * aw_s[j_pw];
        #pragma unroll
        for (int off = 16; off; off >>= 1)
            part += __shfl_xor_sync(0xffffffffu, part, off);
        if (lane == 0) lpart[wid] = part;
        __syncthreads();                                 // sync2: h + partials ready

        // online softmax scalars (attn_b dropped: softmax shift-invariant)
        if (tid < 4) {
            float l = lpart[tid * 4] + lpart[tid * 4 + 1]
                    + lpart[tid * 4 + 2] + lpart[tid * 4 + 3];
            float mold = mrow[tid];
            float mnew = fmaxf(mold, l);
            float al   = __expf(mold - mnew);            // 0 on first step
            float pv   = __expf(l - mnew);
            mrow[tid]  = mnew;
            srow[tid]  = srow[tid] * al + pv;
            alph[tid]  = al;
            prow[tid]  = pv;
        }
        __syncthreads();                                 // sync3: scalars ready

        // online pooled accumulate (h in register)
        accp = accp * alph[r_pw] + prow[r_pw] * hv;
        // next matvec reads h_s (stable since sync2) and rewrites gts
        // (last read before sync2); alph/prow next overwritten after
        // sync2(t+1) -> two barriers separate the hazards.
    }

    // epilogue: pooled = acc/s ; score = pooled . (fc_w/sigma) + fc_b
    float po = accp / srow[r_pw];
    float part = po * fw_s[j_pw];
    #pragma unroll
    for (int off = 16; off; off >>= 1)
        part += __shfl_xor_sync(0xffffffffu, part, off);
    if (lane == 0) lpart[wid] = part;
    __syncthreads();
    if (tid < 4) {
        float sc = lpart[tid * 4] + lpart[tid * 4 + 1]
                 + lpart[tid * 4 + 2] + lpart[tid * 4 + 3];
        out[b0 + tid] = sc * g_inv_arr[2] + fc_b[0];
    }
}

// ---------------------------------------------------------------------------
extern "C" void kernel_launch(void* const* d_in, const int* in_sizes, int n_in,
                              void* d_out, int out_size)
{
    const float* x      = (const float*)d_in[0];
    const float* w_ih   = (const float*)d_in[1];
    const float* u_ih   = (const float*)d_in[2];
    const float* w_hh   = (const float*)d_in[3];
    const float* u_hh   = (const float*)d_in[4];
    const float* b_ih   = (const float*)d_in[5];
    const float* b_hh   = (const float*)d_in[6];
    const float* attn_w = (const float*)d_in[7];
    // d_in[8] = attn_b (softmax shift-invariant, unused)
    const float* fc_w   = (const float*)d_in[9];
    const float* u_fc   = (const float*)d_in[10];
    const float* fc_b   = (const float*)d_in[11];
    float* out = (float*)d_out;

    std_kernel<<<T_STEPS, 256>>>(x);
    prep_kernel<<<1, 512>>>(w_ih, u_ih, w_hh, u_hh, b_ih, b_hh, fc_w, u_fc);
    gates_kernel<<<(BATCH * T_STEPS) / 32, 256>>>(x);

    int smem = (HID / 4) * GATES * 2 * 4   // bf16-quad weights: 128 KB
             + 4 * HID * 4                 // h_s
             + 4 * GATES * 4               // gts
             + 2 * HID * 4                 // aw_s, fw_s
             + 16 * 4                      // lpart
             + 16 * 4;                     // scalars
    cudaFuncSetAttribute(lstm_kernel, cudaFuncAttributeMaxDynamicSharedMemorySize, smem);
    lstm_kernel<<<BATCH / 4, 512, smem>>>(attn_w, fc_w, fc_b, out);
}